// round 2
// baseline (speedup 1.0000x reference)
#include <cuda_runtime.h>
#include <cstdint>

#define Hdim 256
#define Sdim 512
#define Bdim 256
#define G3   768

// 402 MB scratch for precomputed input-gate activations gi[b*S + t][768]
__device__ float g_gi[(size_t)Bdim * Sdim * G3];

// ---- f32x2 helpers (FFMA2 on sm_103a) -------------------------------------
typedef unsigned long long u64;
__device__ __forceinline__ u64 pack2(float lo, float hi) {
    u64 r; asm("mov.b64 %0,{%1,%2};" : "=l"(r) : "f"(lo), "f"(hi)); return r;
}
__device__ __forceinline__ void unpack2(u64 v, float& lo, float& hi) {
    asm("mov.b64 {%0,%1},%2;" : "=f"(lo), "=f"(hi) : "l"(v));
}
__device__ __forceinline__ u64 ffma2(u64 a, u64 b, u64 c) {
    u64 d; asm("fma.rn.f32x2 %0,%1,%2,%3;" : "=l"(d) : "l"(a), "l"(b), "l"(c));
    return d;
}

// ---------------------------------------------------------------------------
// Kernel 1: gi = x @ W_ih^T + b_ih, FFMA2 micro-kernel.
// 128(M) x 128(N) x 32(K) tile, 256 threads, 8x8 micro-tile (4 f32x2 per row).
// ---------------------------------------------------------------------------
__global__ __launch_bounds__(256) void gi_gemm_kernel(const float* __restrict__ seq,
                                                      const float* __restrict__ W_ih,
                                                      const float* __restrict__ b_ih) {
    __shared__ __align__(16) float As[32 * 128];
    __shared__ __align__(16) float Ws[32 * 132];
    const int tid = threadIdx.x;
    const int b   = blockIdx.x >> 2;
    const int t0  = (blockIdx.x & 3) * 128;
    const int n0  = blockIdx.y * 128;
    const float* seqb = seq + (size_t)b * (Hdim * Sdim);

    const int tm = (tid & 15) * 4;
    const int tn = (tid >> 4) * 4;
    const int lane = tid & 31, wp = tid >> 5;

    u64 acc2[8][4];
#pragma unroll
    for (int i = 0; i < 8; ++i)
#pragma unroll
        for (int j = 0; j < 4; ++j) acc2[i][j] = 0ull;

    for (int kt = 0; kt < 8; ++kt) {
        int pos = tid;
#pragma unroll
        for (int i = 0; i < 4; ++i, pos += 256) {
            int k  = pos >> 5;
            int mq = (pos & 31) << 2;
            float4 v = *(const float4*)(seqb + (size_t)(kt * 32 + k) * Sdim + t0 + mq);
            *(float4*)&As[k * 128 + mq] = v;
        }
#pragma unroll
        for (int i = 0; i < 16; ++i) {
            int n = wp * 16 + i;
            Ws[lane * 132 + n] = W_ih[(size_t)(n0 + n) * Hdim + kt * 32 + lane];
        }
        __syncthreads();
#pragma unroll
        for (int kk = 0; kk < 32; ++kk) {
            float4 a0 = *(const float4*)&As[kk * 128 + tm];
            float4 a1 = *(const float4*)&As[kk * 128 + tm + 64];
            ulonglong2 w0 = *(const ulonglong2*)&Ws[kk * 132 + tn];
            ulonglong2 w1 = *(const ulonglong2*)&Ws[kk * 132 + tn + 64];
            float am[8] = {a0.x, a0.y, a0.z, a0.w, a1.x, a1.y, a1.z, a1.w};
#pragma unroll
            for (int i = 0; i < 8; ++i) {
                u64 a2 = pack2(am[i], am[i]);
                acc2[i][0] = ffma2(a2, w0.x, acc2[i][0]);
                acc2[i][1] = ffma2(a2, w0.y, acc2[i][1]);
                acc2[i][2] = ffma2(a2, w1.x, acc2[i][2]);
                acc2[i][3] = ffma2(a2, w1.y, acc2[i][3]);
            }
        }
        __syncthreads();
    }

    float4 bias0 = *(const float4*)&b_ih[n0 + tn];
    float4 bias1 = *(const float4*)&b_ih[n0 + tn + 64];
    float bs[8] = {bias0.x, bias0.y, bias0.z, bias0.w, bias1.x, bias1.y, bias1.z, bias1.w};
#pragma unroll
    for (int i = 0; i < 8; ++i) {
        int m = (i < 4) ? (tm + i) : (tm + 60 + i);
        float c[8];
#pragma unroll
        for (int jp = 0; jp < 4; ++jp) unpack2(acc2[i][jp], c[2 * jp], c[2 * jp + 1]);
        float* orow = g_gi + ((size_t)b * Sdim + t0 + m) * G3 + n0;
        *(float4*)(orow + tn)      = make_float4(c[0] + bs[0], c[1] + bs[1], c[2] + bs[2], c[3] + bs[3]);
        *(float4*)(orow + tn + 64) = make_float4(c[4] + bs[4], c[5] + bs[5], c[6] + bs[6], c[7] + bs[7]);
    }
}

// ---------------------------------------------------------------------------
// Kernel 2: persistent GRU recurrence, v2.
// 32 clusters x 4 CTAs; CTA rank r owns h-dims [64r, 64r+64), 8 batch rows.
// Thread (jt = tid>>2, kq = bit1, bh = bit0): 3 gates x 4 batch rows over a
// 128-wide k chunk, vector LDS + FFMA2, cross-kq reduce via shfl.xor(2).
// W_s layout: row stride 264 floats, chunk stride 132 (odd 16B slot count ->
// conflict-free LDS.128 across (jt,kq) lanes; bh lanes merge as broadcast).
// ---------------------------------------------------------------------------
#define CH   132
#define WRS  264
#define WS_FLOATS (192 * WRS)          // 50688
#define HB_FLOATS (2 * 8 * 256)        // 4096
#define RSM_BYTES ((WS_FLOATS + HB_FLOATS + 8) * 4)   // 219,168 B

__device__ __forceinline__ float sigm(float x) {
    return __fdividef(1.f, 1.f + __expf(-x));
}
__device__ __forceinline__ float tanh_e(float x) {
    return __fdividef(2.f, 1.f + __expf(-2.f * x)) - 1.f;
}

__global__ __launch_bounds__(256, 1) __cluster_dims__(4, 1, 1)
void gru_rec_kernel(const float* __restrict__ tree,
                    const int*   __restrict__ mask,
                    const float* __restrict__ W_hh,
                    const float* __restrict__ b_hh,
                    float*       __restrict__ out) {
    extern __shared__ __align__(16) float sm[];
    float* W_s   = sm;                      // [192][264]
    float* h_buf = sm + WS_FLOATS;          // [2][8][256]
    int*   li_s  = (int*)(h_buf + HB_FLOATS);

    const int tid = threadIdx.x;
    const int r   = blockIdx.x & 3;
    const int b0  = (blockIdx.x >> 2) * 8;

    // W_hh slice -> padded smem layout
    for (int i = tid; i < 192 * 256; i += 256) {
        int row = i >> 8, col = i & 255;
        int grow = (row >> 6) * 256 + r * 64 + (row & 63);
        W_s[row * WRS + (col >> 7) * CH + (col & 127)] = W_hh[(size_t)grow * 256 + col];
    }
    for (int i = tid; i < 8 * 256; i += 256)
        h_buf[i] = tree[(size_t)b0 * 256 + i];
    {
        int bb = tid >> 5, lane = tid & 31;
        int s = 0;
        for (int i = lane; i < 512; i += 32) s += mask[(size_t)(b0 + bb) * 512 + i];
#pragma unroll
        for (int o = 16; o; o >>= 1) s += __shfl_xor_sync(0xffffffffu, s, o);
        if (lane == 0) li_s[bb] = (s > 0) ? (s - 1) : 0;
    }
    __syncthreads();
    asm volatile("barrier.cluster.arrive.aligned;" ::: "memory");
    asm volatile("barrier.cluster.wait.aligned;" ::: "memory");

    const int jt = tid >> 2;
    const int kq = (tid >> 1) & 1;
    const int bh = tid & 1;
    const int kglob = r * 64 + jt;

    const float* wr = W_s + jt * WRS + kq * CH;
    const float* wz = wr + 64 * WRS;
    const float* wn = wr + 128 * WRS;
    const float bhr = b_hh[kglob];
    const float bhz = b_hh[256 + kglob];
    const float bhn = b_hh[512 + kglob];

    // DSMEM peer bases (mapa once)
    uint32_t hb_u32;
    asm("{ .reg .u64 t0; cvta.to.shared.u64 t0, %1; cvt.u32.u64 %0, t0; }"
        : "=r"(hb_u32) : "l"(h_buf));
    uint32_t peer[4];
#pragma unroll
    for (int q = 0; q < 4; ++q)
        asm("mapa.shared::cluster.u32 %0, %1, %2;" : "=r"(peer[q]) : "r"(hb_u32), "r"(q));

    // per-thread epilogue state (holders: kq==0)
    int li_r[4];
    const float* gp[4];
#pragma unroll
    for (int i = 0; i < 4; ++i) {
        int b = bh * 4 + i;
        li_r[i] = li_s[b];
        gp[i] = g_gi + ((size_t)(b0 + b) * Sdim) * G3 + kglob;
    }

    int p = 0;
    for (int t = 0; t < Sdim; ++t) {
        // gi prefetch (holders only), hidden under the dot phase
        float gr[4], gz[4], gn[4];
        if (kq == 0) {
#pragma unroll
            for (int i = 0; i < 4; ++i) {
                const float* g = gp[i];
                gr[i] = __ldg(g); gz[i] = __ldg(g + 256); gn[i] = __ldg(g + 512);
                gp[i] += G3;
            }
        }

        const float* hb2 = h_buf + p * 2048 + kq * 128 + bh * 1024;
        u64 ar[4] = {0,0,0,0}, az[4] = {0,0,0,0}, an[4] = {0,0,0,0};
#pragma unroll 8
        for (int j = 0; j < 32; ++j) {
            ulonglong2 wrv = *(const ulonglong2*)(wr + 4 * j);
            ulonglong2 wzv = *(const ulonglong2*)(wz + 4 * j);
            ulonglong2 wnv = *(const ulonglong2*)(wn + 4 * j);
#pragma unroll
            for (int b4 = 0; b4 < 4; ++b4) {
                ulonglong2 hv = *(const ulonglong2*)(hb2 + b4 * 256 + 4 * j);
                ar[b4] = ffma2(wrv.x, hv.x, ar[b4]);
                ar[b4] = ffma2(wrv.y, hv.y, ar[b4]);
                az[b4] = ffma2(wzv.x, hv.x, az[b4]);
                az[b4] = ffma2(wzv.y, hv.y, az[b4]);
                an[b4] = ffma2(wnv.x, hv.x, an[b4]);
                an[b4] = ffma2(wnv.y, hv.y, an[b4]);
            }
        }
        // horizontal + cross-kq reduce (xor lane bit1)
        float sr[4], sz[4], sn[4];
#pragma unroll
        for (int b4 = 0; b4 < 4; ++b4) {
            float lo, hi;
            unpack2(ar[b4], lo, hi); sr[b4] = lo + hi;
            unpack2(az[b4], lo, hi); sz[b4] = lo + hi;
            unpack2(an[b4], lo, hi); sn[b4] = lo + hi;
        }
#pragma unroll
        for (int b4 = 0; b4 < 4; ++b4) {
            sr[b4] += __shfl_xor_sync(0xffffffffu, sr[b4], 2);
            sz[b4] += __shfl_xor_sync(0xffffffffu, sz[b4], 2);
            sn[b4] += __shfl_xor_sync(0xffffffffu, sn[b4], 2);
        }

        int pn = p ^ 1;
        if (kq == 0) {
#pragma unroll
            for (int i = 0; i < 4; ++i) {
                int b = bh * 4 + i;
                float hold = h_buf[p * 2048 + b * 256 + kglob];
                float rg = sigm(gr[i] + bhr + sr[i]);
                float zg = sigm(gz[i] + bhz + sz[i]);
                float ng = tanh_e(fmaf(rg, sn[i] + bhn, gn[i]));
                float hn = fmaf(zg, hold - ng, ng);
                if (t == li_r[i]) out[(size_t)(b0 + b) * 256 + kglob] = hn;
                uint32_t off = (uint32_t)((pn * 2048 + b * 256 + kglob) * 4);
#pragma unroll
                for (int q = 0; q < 4; ++q)
                    asm volatile("st.shared::cluster.f32 [%0], %1;"
                                 :: "r"(peer[q] + off), "f"(hn) : "memory");
            }
        }
        asm volatile("barrier.cluster.arrive.aligned;" ::: "memory");
        asm volatile("barrier.cluster.wait.aligned;" ::: "memory");
        p = pn;
    }
}

// ---------------------------------------------------------------------------
extern "C" void kernel_launch(void* const* d_in, const int* in_sizes, int n_in,
                              void* d_out, int out_size) {
    const float* tree  = (const float*)d_in[0];
    const float* seq   = (const float*)d_in[1];
    const int*   mask  = (const int*)  d_in[2];
    const float* W_ih  = (const float*)d_in[3];
    const float* W_hh  = (const float*)d_in[4];
    const float* b_ih  = (const float*)d_in[5];
    const float* b_hh  = (const float*)d_in[6];
    float* out = (float*)d_out;

    dim3 g1((Bdim * Sdim) / 128, G3 / 128);
    gi_gemm_kernel<<<g1, 256>>>(seq, W_ih, b_ih);

    cudaFuncSetAttribute(gru_rec_kernel,
                         cudaFuncAttributeMaxDynamicSharedMemorySize, RSM_BYTES);
    gru_rec_kernel<<<128, 256, RSM_BYTES>>>(tree, mask, W_hh, b_hh, out);
}

// round 3
// speedup vs baseline: 2.6801x; 2.6801x over previous
#include <cuda_runtime.h>
#include <cstdint>

#define Hdim 256
#define Sdim 512
#define Bdim 256
#define G3   768

// 402 MB scratch for precomputed input-gate activations gi[b*S + t][768]
__device__ float g_gi[(size_t)Bdim * Sdim * G3];

// ---- f32x2 helpers (FFMA2 on sm_103a) -------------------------------------
typedef unsigned long long u64;
__device__ __forceinline__ void unpack2(u64 v, float& lo, float& hi) {
    asm("mov.b64 {%0,%1},%2;" : "=f"(lo), "=f"(hi) : "l"(v));
}
__device__ __forceinline__ u64 ffma2(u64 a, u64 b, u64 c) {
    u64 d; asm("fma.rn.f32x2 %0,%1,%2,%3;" : "=l"(d) : "l"(a), "l"(b), "l"(c));
    return d;
}

// ---------------------------------------------------------------------------
// Kernel 1: gi = x @ W_ih^T + b_ih (v1 version — known 1.44 ms).
// Tile: 128(M) x 128(N) x 32(K), 256 threads, 8x8 scalar micro-tile.
// ---------------------------------------------------------------------------
__global__ __launch_bounds__(256) void gi_gemm_kernel(const float* __restrict__ seq,
                                                      const float* __restrict__ W_ih,
                                                      const float* __restrict__ b_ih) {
    __shared__ float As[32 * 128];
    __shared__ float Ws[32 * 132];
    const int tid = threadIdx.x;
    const int b   = blockIdx.x >> 2;
    const int t0  = (blockIdx.x & 3) * 128;
    const int n0  = blockIdx.y * 128;
    const float* seqb = seq + (size_t)b * (Hdim * Sdim);

    const int tm = (tid & 15) * 4;
    const int tn = (tid >> 4) * 4;
    const int lane = tid & 31, wp = tid >> 5;

    float acc[8][8];
#pragma unroll
    for (int i = 0; i < 8; ++i)
#pragma unroll
        for (int j = 0; j < 8; ++j) acc[i][j] = 0.f;

    for (int kt = 0; kt < 8; ++kt) {
        int pos = tid;
#pragma unroll
        for (int i = 0; i < 4; ++i, pos += 256) {
            int k  = pos >> 5;
            int mq = (pos & 31) << 2;
            float4 v = *(const float4*)(seqb + (size_t)(kt * 32 + k) * Sdim + t0 + mq);
            *(float4*)&As[k * 128 + mq] = v;
        }
#pragma unroll
        for (int i = 0; i < 16; ++i) {
            int n = wp * 16 + i;
            Ws[lane * 132 + n] = W_ih[(size_t)(n0 + n) * Hdim + kt * 32 + lane];
        }
        __syncthreads();
#pragma unroll
        for (int kk = 0; kk < 32; ++kk) {
            float4 a0 = *(const float4*)&As[kk * 128 + tm];
            float4 a1 = *(const float4*)&As[kk * 128 + tm + 64];
            float4 w0 = *(const float4*)&Ws[kk * 132 + tn];
            float4 w1 = *(const float4*)&Ws[kk * 132 + tn + 64];
            float am[8] = {a0.x, a0.y, a0.z, a0.w, a1.x, a1.y, a1.z, a1.w};
            float wn[8] = {w0.x, w0.y, w0.z, w0.w, w1.x, w1.y, w1.z, w1.w};
#pragma unroll
            for (int i = 0; i < 8; ++i)
#pragma unroll
                for (int j = 0; j < 8; ++j) acc[i][j] = fmaf(am[i], wn[j], acc[i][j]);
        }
        __syncthreads();
    }

    float4 bias0 = *(const float4*)&b_ih[n0 + tn];
    float4 bias1 = *(const float4*)&b_ih[n0 + tn + 64];
    float bs[8] = {bias0.x, bias0.y, bias0.z, bias0.w, bias1.x, bias1.y, bias1.z, bias1.w};
#pragma unroll
    for (int i = 0; i < 8; ++i) {
        int m = (i < 4) ? (tm + i) : (tm + 60 + i);
        float* orow = g_gi + ((size_t)b * Sdim + t0 + m) * G3 + n0;
        *(float4*)(orow + tn)      = make_float4(acc[i][0] + bs[0], acc[i][1] + bs[1],
                                                 acc[i][2] + bs[2], acc[i][3] + bs[3]);
        *(float4*)(orow + tn + 64) = make_float4(acc[i][4] + bs[4], acc[i][5] + bs[5],
                                                 acc[i][6] + bs[6], acc[i][7] + bs[7]);
    }
}

// ---------------------------------------------------------------------------
// Kernel 2: persistent GRU recurrence, v3 = v2 dataflow + conflict-free layout.
// W_s row stride 268 fl, chunk stride 132 fl: 16B-group = (3*jt + kq) mod 8 ->
//   each group hit exactly twice across the 16 distinct lane addrs -> 2 cyc/LDS.128.
// h_buf row stride 268 fl, chunk stride 132 fl: per-instr groups
//   {3b4, 3b4+1, 3b4+4, 3b4+5} -> 4 distinct -> 1 cyc/LDS.128.
// ---------------------------------------------------------------------------
#define CH    132
#define WRS   268
#define HRS   268
#define WS_FLOATS (192 * WRS)            // 51456
#define HB_FLOATS (2 * 8 * HRS)          // 4288
#define RSM_BYTES ((WS_FLOATS + HB_FLOATS + 8) * 4)   // 223,008 B

__device__ __forceinline__ float sigm(float x) {
    return __fdividef(1.f, 1.f + __expf(-x));
}
__device__ __forceinline__ float tanh_e(float x) {
    return __fdividef(2.f, 1.f + __expf(-2.f * x)) - 1.f;
}
__device__ __forceinline__ int hpos(int k) {        // padded column of h element k
    return (k >> 7) * CH + (k & 127);
}

__global__ __launch_bounds__(256, 1) __cluster_dims__(4, 1, 1)
void gru_rec_kernel(const float* __restrict__ tree,
                    const int*   __restrict__ mask,
                    const float* __restrict__ W_hh,
                    const float* __restrict__ b_hh,
                    float*       __restrict__ out) {
    extern __shared__ __align__(16) float sm[];
    float* W_s   = sm;                      // [192][268] (cols padded: 2x132)
    float* h_buf = sm + WS_FLOATS;          // [2][8][268]
    int*   li_s  = (int*)(h_buf + HB_FLOATS);

    const int tid = threadIdx.x;
    const int r   = blockIdx.x & 3;
    const int b0  = (blockIdx.x >> 2) * 8;

    // W_hh slice -> padded smem layout. row = gate*64 + jt
    for (int i = tid; i < 192 * 256; i += 256) {
        int row = i >> 8, col = i & 255;
        int grow = (row >> 6) * 256 + r * 64 + (row & 63);
        W_s[row * WRS + hpos(col)] = W_hh[(size_t)grow * 256 + col];
    }
    for (int i = tid; i < 8 * 256; i += 256) {
        int row = i >> 8, col = i & 255;
        h_buf[row * HRS + hpos(col)] = tree[(size_t)b0 * 256 + i];
    }
    {
        int bb = tid >> 5, lane = tid & 31;
        int s = 0;
        for (int i = lane; i < 512; i += 32) s += mask[(size_t)(b0 + bb) * 512 + i];
#pragma unroll
        for (int o = 16; o; o >>= 1) s += __shfl_xor_sync(0xffffffffu, s, o);
        if (lane == 0) li_s[bb] = (s > 0) ? (s - 1) : 0;
    }
    __syncthreads();
    asm volatile("barrier.cluster.arrive.aligned;" ::: "memory");
    asm volatile("barrier.cluster.wait.aligned;" ::: "memory");

    const int jt = tid >> 2;       // owned h-dim (local)
    const int kq = (tid >> 1) & 1; // k half (0: k<128, 1: k>=128)
    const int bh = tid & 1;        // batch half (4 rows each)
    const int kglob = r * 64 + jt;

    const float* wr = W_s + jt * WRS + kq * CH;
    const float* wz = wr + 64 * WRS;
    const float* wn = wr + 128 * WRS;
    const float bhr = b_hh[kglob];
    const float bhz = b_hh[256 + kglob];
    const float bhn = b_hh[512 + kglob];

    uint32_t hb_u32;
    asm("{ .reg .u64 t0; cvta.to.shared.u64 t0, %1; cvt.u32.u64 %0, t0; }"
        : "=r"(hb_u32) : "l"(h_buf));
    uint32_t peer[4];
#pragma unroll
    for (int q = 0; q < 4; ++q)
        asm("mapa.shared::cluster.u32 %0, %1, %2;" : "=r"(peer[q]) : "r"(hb_u32), "r"(q));

    int li_r[4];
    const float* gp[4];
#pragma unroll
    for (int i = 0; i < 4; ++i) {
        int b = bh * 4 + i;
        li_r[i] = li_s[b];
        gp[i] = g_gi + ((size_t)(b0 + b) * Sdim) * G3 + kglob;
    }
    const int hcol = hpos(kglob);

    int p = 0;
    for (int t = 0; t < Sdim; ++t) {
        // gi prefetch (epilogue holders = kq==0 lanes), hidden under dot phase
        float gr[4], gz[4], gn[4];
        if (kq == 0) {
#pragma unroll
            for (int i = 0; i < 4; ++i) {
                const float* g = gp[i];
                gr[i] = __ldg(g); gz[i] = __ldg(g + 256); gn[i] = __ldg(g + 512);
                gp[i] += G3;
            }
        }

        const float* hb2 = h_buf + p * (8 * HRS) + bh * (4 * HRS) + kq * CH;
        u64 ar[4] = {0,0,0,0}, az[4] = {0,0,0,0}, an[4] = {0,0,0,0};
#pragma unroll 8
        for (int j = 0; j < 32; ++j) {
            ulonglong2 wrv = *(const ulonglong2*)(wr + 4 * j);
            ulonglong2 wzv = *(const ulonglong2*)(wz + 4 * j);
            ulonglong2 wnv = *(const ulonglong2*)(wn + 4 * j);
#pragma unroll
            for (int b4 = 0; b4 < 4; ++b4) {
                ulonglong2 hv = *(const ulonglong2*)(hb2 + b4 * HRS + 4 * j);
                ar[b4] = ffma2(wrv.x, hv.x, ar[b4]);
                ar[b4] = ffma2(wrv.y, hv.y, ar[b4]);
                az[b4] = ffma2(wzv.x, hv.x, az[b4]);
                az[b4] = ffma2(wzv.y, hv.y, az[b4]);
                an[b4] = ffma2(wnv.x, hv.x, an[b4]);
                an[b4] = ffma2(wnv.y, hv.y, an[b4]);
            }
        }
        // horizontal + cross-kq reduce (xor lane bit1)
        float sr[4], sz[4], sn[4];
#pragma unroll
        for (int b4 = 0; b4 < 4; ++b4) {
            float lo, hi;
            unpack2(ar[b4], lo, hi); sr[b4] = lo + hi;
            unpack2(az[b4], lo, hi); sz[b4] = lo + hi;
            unpack2(an[b4], lo, hi); sn[b4] = lo + hi;
            sr[b4] += __shfl_xor_sync(0xffffffffu, sr[b4], 2);
            sz[b4] += __shfl_xor_sync(0xffffffffu, sz[b4], 2);
            sn[b4] += __shfl_xor_sync(0xffffffffu, sn[b4], 2);
        }

        int pn = p ^ 1;
        if (kq == 0) {
#pragma unroll
            for (int i = 0; i < 4; ++i) {
                int b = bh * 4 + i;
                float hold = h_buf[p * (8 * HRS) + b * HRS + hcol];
                float rg = sigm(gr[i] + bhr + sr[i]);
                float zg = sigm(gz[i] + bhz + sz[i]);
                float ng = tanh_e(fmaf(rg, sn[i] + bhn, gn[i]));
                float hn = fmaf(zg, hold - ng, ng);
                if (t == li_r[i]) out[(size_t)(b0 + b) * 256 + kglob] = hn;
                uint32_t off = (uint32_t)((pn * (8 * HRS) + b * HRS + hcol) * 4);
#pragma unroll
                for (int q = 0; q < 4; ++q)
                    asm volatile("st.shared::cluster.f32 [%0], %1;"
                                 :: "r"(peer[q] + off), "f"(hn) : "memory");
            }
        }
        asm volatile("barrier.cluster.arrive.aligned;" ::: "memory");
        asm volatile("barrier.cluster.wait.aligned;" ::: "memory");
        p = pn;
    }
}

// ---------------------------------------------------------------------------
extern "C" void kernel_launch(void* const* d_in, const int* in_sizes, int n_in,
                              void* d_out, int out_size) {
    const float* tree  = (const float*)d_in[0];
    const float* seq   = (const float*)d_in[1];
    const int*   mask  = (const int*)  d_in[2];
    const float* W_ih  = (const float*)d_in[3];
    const float* W_hh  = (const float*)d_in[4];
    const float* b_ih  = (const float*)d_in[5];
    const float* b_hh  = (const float*)d_in[6];
    float* out = (float*)d_out;

    dim3 g1((Bdim * Sdim) / 128, G3 / 128);
    gi_gemm_kernel<<<g1, 256>>>(seq, W_ih, b_ih);

    cudaFuncSetAttribute(gru_rec_kernel,
                         cudaFuncAttributeMaxDynamicSharedMemorySize, RSM_BYTES);
    gru_rec_kernel<<<128, 256, RSM_BYTES>>>(tree, mask, W_hh, b_hh, out);
}

// round 4
// speedup vs baseline: 2.6857x; 1.0021x over previous
#include <cuda_runtime.h>
#include <cstdint>

#define Hdim 256
#define Sdim 512
#define Bdim 256
#define G3   768

// 402 MB scratch for precomputed input-gate activations gi[b*S + t][768]
__device__ float g_gi[(size_t)Bdim * Sdim * G3];

// ---- f32x2 helpers (FFMA2 on sm_103a) -------------------------------------
typedef unsigned long long u64;
__device__ __forceinline__ void unpack2(u64 v, float& lo, float& hi) {
    asm("mov.b64 {%0,%1},%2;" : "=f"(lo), "=f"(hi) : "l"(v));
}
__device__ __forceinline__ u64 ffma2(u64 a, u64 b, u64 c) {
    u64 d; asm("fma.rn.f32x2 %0,%1,%2,%3;" : "=l"(d) : "l"(a), "l"(b), "l"(c));
    return d;
}

// ---------------------------------------------------------------------------
// Kernel 1: gi = x @ W_ih^T + b_ih (v1 version — known 1.44 ms).
// Tile: 128(M) x 128(N) x 32(K), 256 threads, 8x8 scalar micro-tile.
// ---------------------------------------------------------------------------
__global__ __launch_bounds__(256) void gi_gemm_kernel(const float* __restrict__ seq,
                                                      const float* __restrict__ W_ih,
                                                      const float* __restrict__ b_ih) {
    __shared__ float As[32 * 128];
    __shared__ float Ws[32 * 132];
    const int tid = threadIdx.x;
    const int b   = blockIdx.x >> 2;
    const int t0  = (blockIdx.x & 3) * 128;
    const int n0  = blockIdx.y * 128;
    const float* seqb = seq + (size_t)b * (Hdim * Sdim);

    const int tm = (tid & 15) * 4;
    const int tn = (tid >> 4) * 4;
    const int lane = tid & 31, wp = tid >> 5;

    float acc[8][8];
#pragma unroll
    for (int i = 0; i < 8; ++i)
#pragma unroll
        for (int j = 0; j < 8; ++j) acc[i][j] = 0.f;

    for (int kt = 0; kt < 8; ++kt) {
        int pos = tid;
#pragma unroll
        for (int i = 0; i < 4; ++i, pos += 256) {
            int k  = pos >> 5;
            int mq = (pos & 31) << 2;
            float4 v = *(const float4*)(seqb + (size_t)(kt * 32 + k) * Sdim + t0 + mq);
            *(float4*)&As[k * 128 + mq] = v;
        }
#pragma unroll
        for (int i = 0; i < 16; ++i) {
            int n = wp * 16 + i;
            Ws[lane * 132 + n] = W_ih[(size_t)(n0 + n) * Hdim + kt * 32 + lane];
        }
        __syncthreads();
#pragma unroll
        for (int kk = 0; kk < 32; ++kk) {
            float4 a0 = *(const float4*)&As[kk * 128 + tm];
            float4 a1 = *(const float4*)&As[kk * 128 + tm + 64];
            float4 w0 = *(const float4*)&Ws[kk * 132 + tn];
            float4 w1 = *(const float4*)&Ws[kk * 132 + tn + 64];
            float am[8] = {a0.x, a0.y, a0.z, a0.w, a1.x, a1.y, a1.z, a1.w};
            float wn[8] = {w0.x, w0.y, w0.z, w0.w, w1.x, w1.y, w1.z, w1.w};
#pragma unroll
            for (int i = 0; i < 8; ++i)
#pragma unroll
                for (int j = 0; j < 8; ++j) acc[i][j] = fmaf(am[i], wn[j], acc[i][j]);
        }
        __syncthreads();
    }

    float4 bias0 = *(const float4*)&b_ih[n0 + tn];
    float4 bias1 = *(const float4*)&b_ih[n0 + tn + 64];
    float bs[8] = {bias0.x, bias0.y, bias0.z, bias0.w, bias1.x, bias1.y, bias1.z, bias1.w};
#pragma unroll
    for (int i = 0; i < 8; ++i) {
        int m = (i < 4) ? (tm + i) : (tm + 60 + i);
        float* orow = g_gi + ((size_t)b * Sdim + t0 + m) * G3 + n0;
        *(float4*)(orow + tn)      = make_float4(acc[i][0] + bs[0], acc[i][1] + bs[1],
                                                 acc[i][2] + bs[2], acc[i][3] + bs[3]);
        *(float4*)(orow + tn + 64) = make_float4(acc[i][4] + bs[4], acc[i][5] + bs[5],
                                                 acc[i][6] + bs[6], acc[i][7] + bs[7]);
    }
}

// ---------------------------------------------------------------------------
// Kernel 2: persistent GRU recurrence, v3 = v2 dataflow + conflict-free layout.
// W_s row stride 268 fl, chunk stride 132 fl: 16B-group = (3*jt + kq) mod 8 ->
//   each group hit exactly twice across the 16 distinct lane addrs -> 2 cyc/LDS.128.
// h_buf row stride 268 fl, chunk stride 132 fl: per-instr groups
//   {3b4, 3b4+1, 3b4+4, 3b4+5} -> 4 distinct -> 1 cyc/LDS.128.
// ---------------------------------------------------------------------------
#define CH    132
#define WRS   268
#define HRS   268
#define WS_FLOATS (192 * WRS)            // 51456
#define HB_FLOATS (2 * 8 * HRS)          // 4288
#define RSM_BYTES ((WS_FLOATS + HB_FLOATS + 8) * 4)   // 223,008 B

__device__ __forceinline__ float sigm(float x) {
    return __fdividef(1.f, 1.f + __expf(-x));
}
__device__ __forceinline__ float tanh_e(float x) {
    return __fdividef(2.f, 1.f + __expf(-2.f * x)) - 1.f;
}
__device__ __forceinline__ int hpos(int k) {        // padded column of h element k
    return (k >> 7) * CH + (k & 127);
}

__global__ __launch_bounds__(256, 1) __cluster_dims__(4, 1, 1)
void gru_rec_kernel(const float* __restrict__ tree,
                    const int*   __restrict__ mask,
                    const float* __restrict__ W_hh,
                    const float* __restrict__ b_hh,
                    float*       __restrict__ out) {
    extern __shared__ __align__(16) float sm[];
    float* W_s   = sm;                      // [192][268] (cols padded: 2x132)
    float* h_buf = sm + WS_FLOATS;          // [2][8][268]
    int*   li_s  = (int*)(h_buf + HB_FLOATS);

    const int tid = threadIdx.x;
    const int r   = blockIdx.x & 3;
    const int b0  = (blockIdx.x >> 2) * 8;

    // W_hh slice -> padded smem layout. row = gate*64 + jt
    for (int i = tid; i < 192 * 256; i += 256) {
        int row = i >> 8, col = i & 255;
        int grow = (row >> 6) * 256 + r * 64 + (row & 63);
        W_s[row * WRS + hpos(col)] = W_hh[(size_t)grow * 256 + col];
    }
    for (int i = tid; i < 8 * 256; i += 256) {
        int row = i >> 8, col = i & 255;
        h_buf[row * HRS + hpos(col)] = tree[(size_t)b0 * 256 + i];
    }
    {
        int bb = tid >> 5, lane = tid & 31;
        int s = 0;
        for (int i = lane; i < 512; i += 32) s += mask[(size_t)(b0 + bb) * 512 + i];
#pragma unroll
        for (int o = 16; o; o >>= 1) s += __shfl_xor_sync(0xffffffffu, s, o);
        if (lane == 0) li_s[bb] = (s > 0) ? (s - 1) : 0;
    }
    __syncthreads();
    asm volatile("barrier.cluster.arrive.aligned;" ::: "memory");
    asm volatile("barrier.cluster.wait.aligned;" ::: "memory");

    const int jt = tid >> 2;       // owned h-dim (local)
    const int kq = (tid >> 1) & 1; // k half (0: k<128, 1: k>=128)
    const int bh = tid & 1;        // batch half (4 rows each)
    const int kglob = r * 64 + jt;

    const float* wr = W_s + jt * WRS + kq * CH;
    const float* wz = wr + 64 * WRS;
    const float* wn = wr + 128 * WRS;
    const float bhr = b_hh[kglob];
    const float bhz = b_hh[256 + kglob];
    const float bhn = b_hh[512 + kglob];

    uint32_t hb_u32;
    asm("{ .reg .u64 t0; cvta.to.shared.u64 t0, %1; cvt.u32.u64 %0, t0; }"
        : "=r"(hb_u32) : "l"(h_buf));
    uint32_t peer[4];
#pragma unroll
    for (int q = 0; q < 4; ++q)
        asm("mapa.shared::cluster.u32 %0, %1, %2;" : "=r"(peer[q]) : "r"(hb_u32), "r"(q));

    int li_r[4];
    const float* gp[4];
#pragma unroll
    for (int i = 0; i < 4; ++i) {
        int b = bh * 4 + i;
        li_r[i] = li_s[b];
        gp[i] = g_gi + ((size_t)(b0 + b) * Sdim) * G3 + kglob;
    }
    const int hcol = hpos(kglob);

    int p = 0;
    for (int t = 0; t < Sdim; ++t) {
        // gi prefetch (epilogue holders = kq==0 lanes), hidden under dot phase
        float gr[4], gz[4], gn[4];
        if (kq == 0) {
#pragma unroll
            for (int i = 0; i < 4; ++i) {
                const float* g = gp[i];
                gr[i] = __ldg(g); gz[i] = __ldg(g + 256); gn[i] = __ldg(g + 512);
                gp[i] += G3;
            }
        }

        const float* hb2 = h_buf + p * (8 * HRS) + bh * (4 * HRS) + kq * CH;
        u64 ar[4] = {0,0,0,0}, az[4] = {0,0,0,0}, an[4] = {0,0,0,0};
#pragma unroll 8
        for (int j = 0; j < 32; ++j) {
            ulonglong2 wrv = *(const ulonglong2*)(wr + 4 * j);
            ulonglong2 wzv = *(const ulonglong2*)(wz + 4 * j);
            ulonglong2 wnv = *(const ulonglong2*)(wn + 4 * j);
#pragma unroll
            for (int b4 = 0; b4 < 4; ++b4) {
                ulonglong2 hv = *(const ulonglong2*)(hb2 + b4 * HRS + 4 * j);
                ar[b4] = ffma2(wrv.x, hv.x, ar[b4]);
                ar[b4] = ffma2(wrv.y, hv.y, ar[b4]);
                az[b4] = ffma2(wzv.x, hv.x, az[b4]);
                az[b4] = ffma2(wzv.y, hv.y, az[b4]);
                an[b4] = ffma2(wnv.x, hv.x, an[b4]);
                an[b4] = ffma2(wnv.y, hv.y, an[b4]);
            }
        }
        // horizontal + cross-kq reduce (xor lane bit1)
        float sr[4], sz[4], sn[4];
#pragma unroll
        for (int b4 = 0; b4 < 4; ++b4) {
            float lo, hi;
            unpack2(ar[b4], lo, hi); sr[b4] = lo + hi;
            unpack2(az[b4], lo, hi); sz[b4] = lo + hi;
            unpack2(an[b4], lo, hi); sn[b4] = lo + hi;
            sr[b4] += __shfl_xor_sync(0xffffffffu, sr[b4], 2);
            sz[b4] += __shfl_xor_sync(0xffffffffu, sz[b4], 2);
            sn[b4] += __shfl_xor_sync(0xffffffffu, sn[b4], 2);
        }

        int pn = p ^ 1;
        if (kq == 0) {
#pragma unroll
            for (int i = 0; i < 4; ++i) {
                int b = bh * 4 + i;
                float hold = h_buf[p * (8 * HRS) + b * HRS + hcol];
                float rg = sigm(gr[i] + bhr + sr[i]);
                float zg = sigm(gz[i] + bhz + sz[i]);
                float ng = tanh_e(fmaf(rg, sn[i] + bhn, gn[i]));
                float hn = fmaf(zg, hold - ng, ng);
                if (t == li_r[i]) out[(size_t)(b0 + b) * 256 + kglob] = hn;
                uint32_t off = (uint32_t)((pn * (8 * HRS) + b * HRS + hcol) * 4);
#pragma unroll
                for (int q = 0; q < 4; ++q)
                    asm volatile("st.shared::cluster.f32 [%0], %1;"
                                 :: "r"(peer[q] + off), "f"(hn) : "memory");
            }
        }
        asm volatile("barrier.cluster.arrive.aligned;" ::: "memory");
        asm volatile("barrier.cluster.wait.aligned;" ::: "memory");
        p = pn;
    }
}

// ---------------------------------------------------------------------------
extern "C" void kernel_launch(void* const* d_in, const int* in_sizes, int n_in,
                              void* d_out, int out_size) {
    const float* tree  = (const float*)d_in[0];
    const float* seq   = (const float*)d_in[1];
    const int*   mask  = (const int*)  d_in[2];
    const float* W_ih  = (const float*)d_in[3];
    const float* W_hh  = (const float*)d_in[4];
    const float* b_ih  = (const float*)d_in[5];
    const float* b_hh  = (const float*)d_in[6];
    float* out = (float*)d_out;

    dim3 g1((Bdim * Sdim) / 128, G3 / 128);
    gi_gemm_kernel<<<g1, 256>>>(seq, W_ih, b_ih);

    cudaFuncSetAttribute(gru_rec_kernel,
                         cudaFuncAttributeMaxDynamicSharedMemorySize, RSM_BYTES);
    gru_rec_kernel<<<128, 256, RSM_BYTES>>>(tree, mask, W_hh, b_hh, out);
}

// round 5
// speedup vs baseline: 3.0081x; 1.1200x over previous
#include <cuda_runtime.h>
#include <cstdint>

#define Hdim 256
#define Sdim 512
#define Bdim 256
#define G3   768

// 402 MB scratch for precomputed input-gate activations gi[b*S + t][768]
__device__ float g_gi[(size_t)Bdim * Sdim * G3];

// ---- f32x2 helpers ---------------------------------------------------------
typedef unsigned long long u64;
__device__ __forceinline__ u64 pack2(float lo, float hi) {
    u64 r; asm("mov.b64 %0,{%1,%2};" : "=l"(r) : "f"(lo), "f"(hi)); return r;
}
__device__ __forceinline__ void unpack2(u64 v, float& lo, float& hi) {
    asm("mov.b64 {%0,%1},%2;" : "=f"(lo), "=f"(hi) : "l"(v));
}
__device__ __forceinline__ u64 ffma2(u64 a, u64 b, u64 c) {
    u64 d; asm("fma.rn.f32x2 %0,%1,%2,%3;" : "=l"(d) : "l"(a), "l"(b), "l"(c));
    return d;
}

// ---------------------------------------------------------------------------
// Kernel 1: gi = x @ W_ih^T + b_ih (v1 — measured ~1.44 ms). Unchanged.
// ---------------------------------------------------------------------------
__global__ __launch_bounds__(256) void gi_gemm_kernel(const float* __restrict__ seq,
                                                      const float* __restrict__ W_ih,
                                                      const float* __restrict__ b_ih) {
    __shared__ float As[32 * 128];
    __shared__ float Ws[32 * 132];
    const int tid = threadIdx.x;
    const int b   = blockIdx.x >> 2;
    const int t0  = (blockIdx.x & 3) * 128;
    const int n0  = blockIdx.y * 128;
    const float* seqb = seq + (size_t)b * (Hdim * Sdim);

    const int tm = (tid & 15) * 4;
    const int tn = (tid >> 4) * 4;
    const int lane = tid & 31, wp = tid >> 5;

    float acc[8][8];
#pragma unroll
    for (int i = 0; i < 8; ++i)
#pragma unroll
        for (int j = 0; j < 8; ++j) acc[i][j] = 0.f;

    for (int kt = 0; kt < 8; ++kt) {
        int pos = tid;
#pragma unroll
        for (int i = 0; i < 4; ++i, pos += 256) {
            int k  = pos >> 5;
            int mq = (pos & 31) << 2;
            float4 v = *(const float4*)(seqb + (size_t)(kt * 32 + k) * Sdim + t0 + mq);
            *(float4*)&As[k * 128 + mq] = v;
        }
#pragma unroll
        for (int i = 0; i < 16; ++i) {
            int n = wp * 16 + i;
            Ws[lane * 132 + n] = W_ih[(size_t)(n0 + n) * Hdim + kt * 32 + lane];
        }
        __syncthreads();
#pragma unroll
        for (int kk = 0; kk < 32; ++kk) {
            float4 a0 = *(const float4*)&As[kk * 128 + tm];
            float4 a1 = *(const float4*)&As[kk * 128 + tm + 64];
            float4 w0 = *(const float4*)&Ws[kk * 132 + tn];
            float4 w1 = *(const float4*)&Ws[kk * 132 + tn + 64];
            float am[8] = {a0.x, a0.y, a0.z, a0.w, a1.x, a1.y, a1.z, a1.w};
            float wn[8] = {w0.x, w0.y, w0.z, w0.w, w1.x, w1.y, w1.z, w1.w};
#pragma unroll
            for (int i = 0; i < 8; ++i)
#pragma unroll
                for (int j = 0; j < 8; ++j) acc[i][j] = fmaf(am[i], wn[j], acc[i][j]);
        }
        __syncthreads();
    }

    float4 bias0 = *(const float4*)&b_ih[n0 + tn];
    float4 bias1 = *(const float4*)&b_ih[n0 + tn + 64];
    float bs[8] = {bias0.x, bias0.y, bias0.z, bias0.w, bias1.x, bias1.y, bias1.z, bias1.w};
#pragma unroll
    for (int i = 0; i < 8; ++i) {
        int m = (i < 4) ? (tm + i) : (tm + 60 + i);
        float* orow = g_gi + ((size_t)b * Sdim + t0 + m) * G3 + n0;
        *(float4*)(orow + tn)      = make_float4(acc[i][0] + bs[0], acc[i][1] + bs[1],
                                                 acc[i][2] + bs[2], acc[i][3] + bs[3]);
        *(float4*)(orow + tn + 64) = make_float4(acc[i][4] + bs[4], acc[i][5] + bs[5],
                                                 acc[i][6] + bs[6], acc[i][7] + bs[7]);
    }
}

// ---------------------------------------------------------------------------
// Kernel 2: persistent GRU recurrence v5.
// 32 clusters x 4 CTAs; CTA rank r owns h-dims [64r,64r+64), 8 batch rows.
// Thread (jg = 2 jt dims, kc = k-pairs = kc mod 8): all 8 batch rows, pairs
// along k via FFMA2 (no packing movs). Requested smem bytes/step: 452 KB
// (vs 896 KB in v3). Reduce-scatter over kc -> lane owns (b=kc, jt pair).
// W_s row stride 260: jg groups land at bank offsets {0,8,16,24} -> each bank
// hit exactly 2x per W LDS.64 (optimal). h: kc lanes = 8 consecutive u64.
// ---------------------------------------------------------------------------
#define WS 260
#define HS 258
#define WS_FLOATS (192 * WS)      // 49920
#define HB_FLOATS (2 * 8 * HS)    // 4128
#define RSM_BYTES ((WS_FLOATS + HB_FLOATS + 16) * 4)   // 216,256 B

__device__ __forceinline__ float sigm(float x) {
    return __fdividef(1.f, 1.f + __expf(-x));
}
__device__ __forceinline__ float tanh_e(float x) {
    return __fdividef(2.f, 1.f + __expf(-2.f * x)) - 1.f;
}

__global__ __launch_bounds__(256, 1) __cluster_dims__(4, 1, 1)
void gru_rec_kernel(const float* __restrict__ tree,
                    const int*   __restrict__ mask,
                    const float* __restrict__ W_hh,
                    const float* __restrict__ b_hh,
                    float*       __restrict__ out) {
    extern __shared__ __align__(16) float sm[];
    float* W_s   = sm;                    // [192][260]: row = gate*64 + jt, col = k
    float* h_buf = sm + WS_FLOATS;        // [2][8][258]: [p][b][k]
    int*   li_s  = (int*)(h_buf + HB_FLOATS);

    const int tid = threadIdx.x;
    const int r   = blockIdx.x & 3;
    const int b0  = (blockIdx.x >> 2) * 8;

    for (int i = tid; i < 192 * 256; i += 256) {
        int row = i >> 8, k = i & 255;
        int grow = (row >> 6) * 256 + r * 64 + (row & 63);
        W_s[row * WS + k] = W_hh[(size_t)grow * 256 + k];
    }
    for (int i = tid; i < 8 * 256; i += 256)
        h_buf[(i >> 8) * HS + (i & 255)] = tree[(size_t)b0 * 256 + i];
    {
        int bb = tid >> 5, ln = tid & 31;
        int s = 0;
        for (int i = ln; i < 512; i += 32) s += mask[(size_t)(b0 + bb) * 512 + i];
#pragma unroll
        for (int o = 16; o; o >>= 1) s += __shfl_xor_sync(0xffffffffu, s, o);
        if (ln == 0) li_s[bb] = (s > 0) ? (s - 1) : 0;
    }
    __syncthreads();
    asm volatile("barrier.cluster.arrive.aligned;" ::: "memory");
    asm volatile("barrier.cluster.wait.aligned;" ::: "memory");

    const int lane = tid & 31;
    const int w    = tid >> 5;
    const int kc   = lane & 7;            // k-pair class AND final owned batch row
    const int jg   = w * 4 + (lane >> 3); // 0..31 -> jt pair {2jg, 2jg+1}
    const int kglob = r * 64 + jg * 2;

    const float* wb[3][2];
#pragma unroll
    for (int g = 0; g < 3; ++g)
#pragma unroll
        for (int jl = 0; jl < 2; ++jl)
            wb[g][jl] = W_s + (g * 64 + jg * 2 + jl) * WS + kc * 2;

    const float2 bhr2 = *(const float2*)(b_hh + kglob);
    const float2 bhz2 = *(const float2*)(b_hh + 256 + kglob);
    const float2 bhn2 = *(const float2*)(b_hh + 512 + kglob);
    const int li = li_s[kc];

    uint32_t hb_u32;
    asm("{ .reg .u64 t0; cvta.to.shared.u64 t0, %1; cvt.u32.u64 %0, t0; }"
        : "=r"(hb_u32) : "l"(h_buf));
    uint32_t peer[4];
#pragma unroll
    for (int q = 0; q < 4; ++q)
        asm("mapa.shared::cluster.u32 %0, %1, %2;" : "=r"(peer[q]) : "r"(hb_u32), "r"(q));

    const float* gp = g_gi + ((size_t)(b0 + kc) * Sdim) * G3 + kglob;
    float2 gr2 = *(const float2*)(gp);
    float2 gz2 = *(const float2*)(gp + 256);
    float2 gn2 = *(const float2*)(gp + 512);

    int p = 0;
    for (int t = 0; t < Sdim; ++t) {
        const float* hbp = h_buf + p * (8 * HS) + kc * 2;
        u64 acc[3][2][8];
#pragma unroll
        for (int g = 0; g < 3; ++g)
#pragma unroll
            for (int jl = 0; jl < 2; ++jl)
#pragma unroll
                for (int b = 0; b < 8; ++b) acc[g][jl][b] = 0ull;

#pragma unroll 4
        for (int m = 0; m < 16; ++m) {
            u64 wv[3][2];
#pragma unroll
            for (int g = 0; g < 3; ++g)
#pragma unroll
                for (int jl = 0; jl < 2; ++jl)
                    wv[g][jl] = *(const u64*)(wb[g][jl] + 16 * m);
#pragma unroll
            for (int b = 0; b < 8; ++b) {
                u64 hv = *(const u64*)(hbp + b * HS + 16 * m);
#pragma unroll
                for (int g = 0; g < 3; ++g)
#pragma unroll
                    for (int jl = 0; jl < 2; ++jl)
                        acc[g][jl][b] = ffma2(wv[g][jl], hv, acc[g][jl][b]);
            }
        }

        // ---- reduce-scatter over kc (3 xor rounds), final b = kc ----------
        float s0[3][2][8];
#pragma unroll
        for (int g = 0; g < 3; ++g)
#pragma unroll
            for (int jl = 0; jl < 2; ++jl)
#pragma unroll
                for (int b = 0; b < 8; ++b) {
                    float lo, hi; unpack2(acc[g][jl][b], lo, hi);
                    s0[g][jl][b] = lo + hi;
                }
        const int k0 = kc & 1, k1 = (kc >> 1) & 1, k2 = (kc >> 2) & 1;
        float s1[3][2][4];
#pragma unroll
        for (int g = 0; g < 3; ++g)
#pragma unroll
            for (int jl = 0; jl < 2; ++jl)
#pragma unroll
                for (int b = 0; b < 4; ++b) {
                    float e = s0[g][jl][2 * b], o = s0[g][jl][2 * b + 1];
                    float keep = k0 ? o : e, send = k0 ? e : o;
                    s1[g][jl][b] = keep + __shfl_xor_sync(0xffffffffu, send, 1);
                }
        float s2[3][2][2];
#pragma unroll
        for (int g = 0; g < 3; ++g)
#pragma unroll
            for (int jl = 0; jl < 2; ++jl)
#pragma unroll
                for (int b = 0; b < 2; ++b) {
                    float e = s1[g][jl][2 * b], o = s1[g][jl][2 * b + 1];
                    float keep = k1 ? o : e, send = k1 ? e : o;
                    s2[g][jl][b] = keep + __shfl_xor_sync(0xffffffffu, send, 2);
                }
        float sf[3][2];
#pragma unroll
        for (int g = 0; g < 3; ++g)
#pragma unroll
            for (int jl = 0; jl < 2; ++jl) {
                float e = s2[g][jl][0], o = s2[g][jl][1];
                float keep = k2 ? o : e, send = k2 ? e : o;
                sf[g][jl] = keep + __shfl_xor_sync(0xffffffffu, send, 4);
            }

        // ---- epilogue: batch row kc, dims kglob, kglob+1 -------------------
        const float2 hold2 = *(const float2*)(h_buf + p * (8 * HS) + kc * HS + kglob);
        float r0 = sigm(gr2.x + bhr2.x + sf[0][0]);
        float z0 = sigm(gz2.x + bhz2.x + sf[1][0]);
        float n0 = tanh_e(fmaf(r0, sf[2][0] + bhn2.x, gn2.x));
        float hn0 = fmaf(z0, hold2.x - n0, n0);
        float r1 = sigm(gr2.y + bhr2.y + sf[0][1]);
        float z1 = sigm(gz2.y + bhz2.y + sf[1][1]);
        float n1 = tanh_e(fmaf(r1, sf[2][1] + bhn2.y, gn2.y));
        float hn1 = fmaf(z1, hold2.y - n1, n1);

        if (t == li)
            *(float2*)(out + (size_t)(b0 + kc) * 256 + kglob) = make_float2(hn0, hn1);

        int pn = p ^ 1;
        u64 hv2 = pack2(hn0, hn1);
        uint32_t off = (uint32_t)(((pn * 8 + kc) * HS + kglob) * 4);
#pragma unroll
        for (int q = 0; q < 4; ++q)
            asm volatile("st.shared::cluster.u64 [%0], %1;"
                         :: "r"(peer[q] + off), "l"(hv2) : "memory");

        asm volatile("barrier.cluster.arrive.aligned;" ::: "memory");
        gp += G3;
        if (t + 1 < Sdim) {           // gi(t+1) prefetch hidden under barrier wait
            gr2 = *(const float2*)(gp);
            gz2 = *(const float2*)(gp + 256);
            gn2 = *(const float2*)(gp + 512);
        }
        asm volatile("barrier.cluster.wait.aligned;" ::: "memory");
        p = pn;
    }
}

// ---------------------------------------------------------------------------
extern "C" void kernel_launch(void* const* d_in, const int* in_sizes, int n_in,
                              void* d_out, int out_size) {
    const float* tree  = (const float*)d_in[0];
    const float* seq   = (const float*)d_in[1];
    const int*   mask  = (const int*)  d_in[2];
    const float* W_ih  = (const float*)d_in[3];
    const float* W_hh  = (const float*)d_in[4];
    const float* b_ih  = (const float*)d_in[5];
    const float* b_hh  = (const float*)d_in[6];
    float* out = (float*)d_out;

    dim3 g1((Bdim * Sdim) / 128, G3 / 128);
    gi_gemm_kernel<<<g1, 256>>>(seq, W_ih, b_ih);

    cudaFuncSetAttribute(gru_rec_kernel,
                         cudaFuncAttributeMaxDynamicSharedMemorySize, RSM_BYTES);
    gru_rec_kernel<<<128, 256, RSM_BYTES>>>(tree, mask, W_hh, b_hh, out);
}